// round 13
// baseline (speedup 1.0000x reference)
#include <cuda_runtime.h>
#include <math.h>

#define Bn 4
#define Hh 128
#define Ww 128
#define Aa 96
#define Dd 128
#define Tt 182
#define NITER 10
#define OPN 128.0f

#define HW (Hh*Ww)      // 16384
#define AD (Aa*Dd)      // 12288
#define WP 144          // padded row stride for conv2 inputs (4 left, 12 right pad)

// ---------------- persistent device state ----------------
__device__ __align__(16) float g_dualin[Bn*7*AD];    // ch0-4 dual, ch5 evalop, ch6 y
__device__ __align__(16) float g_primalin[Bn*6*HW];  // ch0-4 primal, ch5 evalop_adj
__device__ __align__(16) float g_pbar[Bn*5*HW];      // primal_bar
__device__ __align__(16) float g_tmp1d[Bn*32*(Aa+2)*WP];  // padded conv1 out (dual)
__device__ __align__(16) float g_tmp1p[Bn*32*(Hh+2)*WP];  // padded conv1 out (primal)
__device__ __align__(16) float g_tmp2[Bn*32*HW];          // conv2 out (unpadded)
__device__ __align__(16) float g_wdup_d[9*32*32*2];  // dup-packed dual conv2 weights
__device__ __align__(16) float g_wdup_p[9*32*32*2];  // dup-packed primal conv2 weights
__device__ float g_cos[Aa], g_sin[Aa];

// ---------------- f32x2 helpers ----------------
__device__ __forceinline__ unsigned long long pack_hi_lo(unsigned long long a, unsigned long long b) {
    // result = ( lo = hi(a), hi = lo(b) )
    unsigned long long r;
    asm("{\n\t"
        ".reg .b32 al, ah, bl, bh;\n\t"
        "mov.b64 {al, ah}, %1;\n\t"
        "mov.b64 {bl, bh}, %2;\n\t"
        "mov.b64 %0, {ah, bl};\n\t"
        "}" : "=l"(r) : "l"(a), "l"(b));
    return r;
}
__device__ __forceinline__ unsigned long long pack_dup(float v) {
    unsigned long long r;
    unsigned int u = __float_as_uint(v);
    asm("mov.b64 %0, {%1, %1};" : "=l"(r) : "r"(u));
    return r;
}
__device__ __forceinline__ void fma2(unsigned long long& d, unsigned long long a, unsigned long long b) {
    asm("fma.rn.f32x2 %0, %1, %2, %0;" : "+l"(d) : "l"(a), "l"(b));
}

// ---------------- init ----------------
__global__ void init_kernel(const float* __restrict__ y) {
    int i = blockIdx.x*blockDim.x + threadIdx.x;
    int stride = gridDim.x*blockDim.x;
    const int N1 = Bn*7*AD, N2 = Bn*6*HW, N3 = Bn*5*HW;
    const int N4 = Bn*32*(Aa+2)*WP, N5 = Bn*32*(Hh+2)*WP;
    for (int idx = i; idx < N1; idx += stride) {
        int b = idx / (7*AD);
        int r = idx % (7*AD);
        int c = r / AD;
        int p = r % AD;
        g_dualin[idx] = (c == 6) ? y[b*AD + p] : 0.0f;
    }
    for (int idx = i; idx < N2; idx += stride) g_primalin[idx] = 0.0f;
    for (int idx = i; idx < N3; idx += stride) g_pbar[idx]     = 0.0f;
    for (int idx = i; idx < N4; idx += stride) g_tmp1d[idx]    = 0.0f;
    for (int idx = i; idx < N5; idx += stride) g_tmp1p[idx]    = 0.0f;
    if (i < Aa) {
        float ang = (float)((double)i * 3.14159265358979323846 / 96.0);
        g_cos[i] = (float)cos((double)ang);
        g_sin[i] = (float)sin((double)ang);
    }
}

// ---------------- weight dup-packer: HWIO (3,3,32,32) -> [ky][ci][kx][co][2] ----------------
__global__ void pack_weights_kernel(const float* __restrict__ w, float* __restrict__ wdup) {
    int i = blockIdx.x*blockDim.x + threadIdx.x;
    if (i >= 9*32*32) return;
    int co = i & 31;
    int r  = i >> 5;
    int kx = r % 3;  r /= 3;
    int ci = r % 32;
    int ky = r / 32;
    float v = w[((ky*3 + kx)*32 + ci)*32 + co];
    int o = ((ky*32 + ci)*3 + kx)*64 + co*2;
    wdup[o]   = v;
    wdup[o+1] = v;
}

// ---------------- radon forward: pbar ch1 -> dualin ch5 ----------------
extern __shared__ float s_dyn[];
__global__ __launch_bounds__(128) void radon_fwd_kernel() {
    float* simg = s_dyn;
    int a = blockIdx.x, b = blockIdx.y, tid = threadIdx.x;
    const float* img = g_pbar + (b*5 + 1)*HW;
    float4* s4 = (float4*)simg;
    const float4* i4 = (const float4*)img;
    for (int i = tid; i < HW/4; i += 128) s4[i] = i4[i];
    __syncthreads();

    float c  = g_cos[a];
    float sn = g_sin[a];
    float sv = (float)tid - 63.5f;
    float acc = 0.0f;
    #pragma unroll 2
    for (int t = 0; t < Tt; t++) {
        float tv = (float)t - 90.5f;
        float xi = sv*c  - tv*sn + 63.5f;
        float yi = sv*sn + tv*c  + 63.5f;
        float x0f = floorf(xi), y0f = floorf(yi);
        float wx = xi - x0f, wy = yi - y0f;
        int x0 = (int)x0f, y0 = (int)y0f;
        int x1 = x0 + 1, y1 = y0 + 1;
        bool vx0 = (x0 >= 0) & (x0 < Ww);
        bool vx1 = (x1 >= 0) & (x1 < Ww);
        bool vy0 = (y0 >= 0) & (y0 < Hh);
        bool vy1 = (y1 >= 0) & (y1 < Hh);
        int cx0 = min(max(x0,0),Ww-1), cx1 = min(max(x1,0),Ww-1);
        int cy0 = min(max(y0,0),Hh-1), cy1 = min(max(y1,0),Hh-1);
        float v00 = (vx0 && vy0) ? simg[cy0*Ww+cx0] : 0.0f;
        float v01 = (vx1 && vy0) ? simg[cy0*Ww+cx1] : 0.0f;
        float v10 = (vx0 && vy1) ? simg[cy1*Ww+cx0] : 0.0f;
        float v11 = (vx1 && vy1) ? simg[cy1*Ww+cx1] : 0.0f;
        acc += v00*(1.0f-wy)*(1.0f-wx) + v01*(1.0f-wy)*wx
             + v10*wy*(1.0f-wx)        + v11*wy*wx;
    }
    g_dualin[(b*7 + 5)*AD + a*Dd + tid] = acc * (1.0f/OPN);
}

// ---------------- radon adjoint: dualin ch0 -> primalin ch5 ----------------
__global__ __launch_bounds__(256) void radon_adj_kernel() {
    float* ssino = s_dyn;
    int b = blockIdx.y, tid = threadIdx.x;
    const float* sino = g_dualin + (b*7 + 0)*AD;
    float4* s4 = (float4*)ssino;
    const float4* i4 = (const float4*)sino;
    for (int i = tid; i < AD/4; i += 256) s4[i] = i4[i];
    __syncthreads();

    #pragma unroll
    for (int pp = 0; pp < 2; pp++) {
        int p = (blockIdx.x*2 + pp)*256 + tid;
        int yy = p >> 7, xx = p & 127;
        float px = (float)xx - 63.5f;
        float py = (float)yy - 63.5f;
        float acc = 0.0f;
        for (int a = 0; a < Aa; a++) {
            float det = px*g_cos[a] + py*g_sin[a] + 63.5f;
            float d0f = floorf(det);
            float w = det - d0f;
            int d0 = (int)d0f;
            int d1 = d0 + 1;
            float v0 = (d0 >= 0 && d0 < Dd) ? ssino[a*Dd + d0] : 0.0f;
            float v1 = (d1 >= 0 && d1 < Dd) ? ssino[a*Dd + d1] : 0.0f;
            acc += v0*(1.0f-w) + v1*w;
        }
        g_primalin[(b*6 + 5)*HW + p] = acc * (1.0f/OPN);
    }
}

// ---------------- conv1: 3x3 (CIN->32) + relu, unpadded in -> PADDED out ----------------
template<int CIN, int HH>
__global__ __launch_bounds__(256) void conv1_kernel(
    const float* __restrict__ in, const float* __restrict__ w,
    const float* __restrict__ bias, float* __restrict__ out)
{
    __shared__ float sw[9*CIN*32];
    __shared__ float sb[32];
    const int NPIX = HH*128;
    int tid = threadIdx.x;
    for (int i = tid; i < 9*CIN*32; i += 256) sw[i] = w[i];
    if (tid < 32) sb[tid] = bias[tid];
    __syncthreads();

    int b = blockIdx.y;
    int p = blockIdx.x*256 + tid;
    int y = p >> 7, x = p & 127;
    const float* inb = in + b*CIN*NPIX;

    float acc[32];
    #pragma unroll
    for (int co = 0; co < 32; co++) acc[co] = sb[co];

    #pragma unroll
    for (int ky = 0; ky < 3; ky++) {
        int iy = y + ky - 1;
        if (iy < 0 || iy >= HH) continue;
        #pragma unroll
        for (int kx = 0; kx < 3; kx++) {
            int ix = x + kx - 1;
            if (ix < 0 || ix >= 128) continue;
            const float* ip = inb + iy*128 + ix;
            const float* wp = sw + (ky*3 + kx)*CIN*32;
            for (int ci = 0; ci < CIN; ci++) {
                float v = __ldg(ip + ci*NPIX);
                const float4* wr = (const float4*)(wp + ci*32);
                #pragma unroll
                for (int q = 0; q < 8; q++) {
                    float4 wv = wr[q];
                    acc[4*q+0] += v*wv.x;
                    acc[4*q+1] += v*wv.y;
                    acc[4*q+2] += v*wv.z;
                    acc[4*q+3] += v*wv.w;
                }
            }
        }
    }
    // padded output: plane (HH+2)*WP, row y+1, col x+4
    float* ob = out + (b*32)*(HH+2)*WP + (y+1)*WP + x + 4;
    #pragma unroll
    for (int co = 0; co < 32; co++) ob[co*(HH+2)*WP] = fmaxf(acc[co], 0.0f);
}

// ---------------- conv2: 3x3 32->32 + relu, f32x2 packed, padded in -> unpadded out ----
// block = 64 threads: 16 pixel-groups (8 px each) x 4 co-groups (8 co each)
// grid = (HH, Bn)
template<int HH>
__global__ __launch_bounds__(64) void conv2_f32x2_kernel(
    const float* __restrict__ in,    // padded [B][32][HH+2][WP]
    const float* __restrict__ wdup,  // [ky][ci][kx][co][2]
    const float* __restrict__ bias,
    float* __restrict__ out)         // [B][32][HH][128]
{
    const int PLANE = (HH+2)*WP;
    int tid = threadIdx.x;
    int pxg = tid >> 2;          // 0..15
    int cg  = tid & 3;           // 0..3
    int x0  = pxg << 3;
    int y   = blockIdx.x;
    int b   = blockIdx.y;

    unsigned long long acc[8][4];
    #pragma unroll
    for (int j = 0; j < 8; j++) {
        unsigned long long bb = pack_dup(__ldg(&bias[cg*8 + j]));
        #pragma unroll
        for (int k = 0; k < 4; k++) acc[j][k] = bb;
    }

    // pointer to (ch0, row y-1+1=y in padded idx, col x0-4): the +4 col pad and
    // the -4 left-read cancel, so base = row start + x0.
    const float* rowbase = in + (b*32)*PLANE + y*WP + x0;

    #pragma unroll 1
    for (int ky = 0; ky < 3; ky++) {
        const float* r = rowbase + ky*WP;   // padded row index y+ky = logical row y+ky-1
        const float* wk = wdup + (ky*32)*3*64 + cg*16;
        #pragma unroll 2
        for (int ci = 0; ci < 32; ci++) {
            const ulonglong2* u = (const ulonglong2*)(r + ci*PLANE);   // cols x0-4 ..
            ulonglong2 U0 = u[0];   // P-2, P-1   (cols x0-4..x0-1)
            ulonglong2 U1 = u[1];   // P0,  P1    (x0..x0+3)
            ulonglong2 U2 = u[2];   // P2,  P3    (x0+4..x0+7)
            ulonglong2 U3 = u[3];   // P4,  P5    (x0+8..x0+11)

            unsigned long long S0 = pack_hi_lo(U0.y, U1.x);
            unsigned long long S1 = pack_hi_lo(U1.x, U1.y);
            unsigned long long S2 = pack_hi_lo(U1.y, U2.x);
            unsigned long long S3 = pack_hi_lo(U2.x, U2.y);
            unsigned long long T3 = pack_hi_lo(U2.y, U3.x);

            const ulonglong2* wp = (const ulonglong2*)(wk + ci*3*64);

            #pragma unroll
            for (int kxi = 0; kxi < 3; kxi++) {
                unsigned long long A0, A1, A2, A3;
                if (kxi == 0)      { A0 = S0;   A1 = S1;   A2 = S2;   A3 = S3; }
                else if (kxi == 1) { A0 = U1.x; A1 = U1.y; A2 = U2.x; A3 = U2.y; }
                else               { A0 = S1;   A1 = S2;   A2 = S3;   A3 = T3; }

                ulonglong2 w01 = wp[kxi*16 + 0];
                ulonglong2 w23 = wp[kxi*16 + 1];
                ulonglong2 w45 = wp[kxi*16 + 2];
                ulonglong2 w67 = wp[kxi*16 + 3];

                fma2(acc[0][0], A0, w01.x); fma2(acc[0][1], A1, w01.x);
                fma2(acc[0][2], A2, w01.x); fma2(acc[0][3], A3, w01.x);
                fma2(acc[1][0], A0, w01.y); fma2(acc[1][1], A1, w01.y);
                fma2(acc[1][2], A2, w01.y); fma2(acc[1][3], A3, w01.y);
                fma2(acc[2][0], A0, w23.x); fma2(acc[2][1], A1, w23.x);
                fma2(acc[2][2], A2, w23.x); fma2(acc[2][3], A3, w23.x);
                fma2(acc[3][0], A0, w23.y); fma2(acc[3][1], A1, w23.y);
                fma2(acc[3][2], A2, w23.y); fma2(acc[3][3], A3, w23.y);
                fma2(acc[4][0], A0, w45.x); fma2(acc[4][1], A1, w45.x);
                fma2(acc[4][2], A2, w45.x); fma2(acc[4][3], A3, w45.x);
                fma2(acc[5][0], A0, w45.y); fma2(acc[5][1], A1, w45.y);
                fma2(acc[5][2], A2, w45.y); fma2(acc[5][3], A3, w45.y);
                fma2(acc[6][0], A0, w67.x); fma2(acc[6][1], A1, w67.x);
                fma2(acc[6][2], A2, w67.x); fma2(acc[6][3], A3, w67.x);
                fma2(acc[7][0], A0, w67.y); fma2(acc[7][1], A1, w67.y);
                fma2(acc[7][2], A2, w67.y); fma2(acc[7][3], A3, w67.y);
            }
        }
    }

    #pragma unroll
    for (int j = 0; j < 8; j++) {
        int co = cg*8 + j;
        float2* op = (float2*)(out + ((b*32 + co)*HH + y)*128 + x0);
        #pragma unroll
        for (int k = 0; k < 4; k++) {
            unsigned long long a = acc[j][k];
            float lo = __uint_as_float((unsigned int)a);
            float hi = __uint_as_float((unsigned int)(a >> 32));
            float2 v;
            v.x = fmaxf(lo, 0.0f);
            v.y = fmaxf(hi, 0.0f);
            op[k] = v;
        }
    }
}

// ---------------- conv3x3 (32->5) + dual update ----------------
__global__ __launch_bounds__(256) void conv_dual_update_kernel(
    const float* __restrict__ in, const float* __restrict__ w,
    const float* __restrict__ bias, const float* __restrict__ sigma)
{
    __shared__ float sw[9*32*5];
    __shared__ float sb[5];
    int tid = threadIdx.x;
    for (int i = tid; i < 9*32*5; i += 256) sw[i] = w[i];
    if (tid < 5) sb[tid] = bias[tid];
    __syncthreads();

    int b = blockIdx.y;
    int p = blockIdx.x*256 + tid;
    int y = p >> 7, x = p & 127;
    const float* inb = in + b*32*AD;

    float acc[5];
    #pragma unroll
    for (int co = 0; co < 5; co++) acc[co] = sb[co];

    #pragma unroll
    for (int ky = 0; ky < 3; ky++) {
        int iy = y + ky - 1;
        if (iy < 0 || iy >= Aa) continue;
        #pragma unroll
        for (int kx = 0; kx < 3; kx++) {
            int ix = x + kx - 1;
            if (ix < 0 || ix >= 128) continue;
            const float* ip = inb + iy*128 + ix;
            const float* wp = sw + (ky*3 + kx)*32*5;
            for (int ci = 0; ci < 32; ci++) {
                float v = __ldg(ip + ci*AD);
                const float* wr = wp + ci*5;
                #pragma unroll
                for (int co = 0; co < 5; co++) acc[co] += v*wr[co];
            }
        }
    }
    float sg = __ldg(sigma);
    #pragma unroll
    for (int co = 0; co < 5; co++) {
        float* dp = g_dualin + (b*7 + co)*AD + p;
        *dp = *dp + sg*acc[co];
    }
}

// ---------------- conv3x3 (32->5) + primal & pbar update ----------------
__global__ __launch_bounds__(256) void conv_primal_update_kernel(
    const float* __restrict__ in, const float* __restrict__ w,
    const float* __restrict__ bias, const float* __restrict__ tau,
    const float* __restrict__ theta)
{
    __shared__ float sw[9*32*5];
    __shared__ float sb[5];
    int tid = threadIdx.x;
    for (int i = tid; i < 9*32*5; i += 256) sw[i] = w[i];
    if (tid < 5) sb[tid] = bias[tid];
    __syncthreads();

    int b = blockIdx.y;
    int p = blockIdx.x*256 + tid;
    int y = p >> 7, x = p & 127;
    const float* inb = in + b*32*HW;

    float acc[5];
    #pragma unroll
    for (int co = 0; co < 5; co++) acc[co] = sb[co];

    #pragma unroll
    for (int ky = 0; ky < 3; ky++) {
        int iy = y + ky - 1;
        if (iy < 0 || iy >= Hh) continue;
        #pragma unroll
        for (int kx = 0; kx < 3; kx++) {
            int ix = x + kx - 1;
            if (ix < 0 || ix >= 128) continue;
            const float* ip = inb + iy*128 + ix;
            const float* wp = sw + (ky*3 + kx)*32*5;
            for (int ci = 0; ci < 32; ci++) {
                float v = __ldg(ip + ci*HW);
                const float* wr = wp + ci*5;
                #pragma unroll
                for (int co = 0; co < 5; co++) acc[co] += v*wr[co];
            }
        }
    }
    float tv = __ldg(tau);
    float th = __ldg(theta);
    #pragma unroll
    for (int co = 0; co < 5; co++) {
        float* pp = g_primalin + (b*6 + co)*HW + p;
        float oldv = *pp;
        float nv = oldv + tv*acc[co];
        *pp = nv;
        g_pbar[(b*5 + co)*HW + p] = nv + th*(nv - oldv);
    }
}

// ---------------- output ----------------
__global__ void output_kernel(float* __restrict__ out) {
    int i = blockIdx.x*blockDim.x + threadIdx.x;
    if (i < Bn*HW) {
        int b = i / HW, p = i % HW;
        out[i] = g_primalin[(b*6 + 0)*HW + p];
    }
}

// ---------------- launch ----------------
extern "C" void kernel_launch(void* const* d_in, const int* in_sizes, int n_in,
                              void* d_out, int out_size)
{
    const float* y     = (const float*)d_in[0];
    const float* sigma = (const float*)d_in[1];
    const float* tau   = (const float*)d_in[2];
    const float* theta = (const float*)d_in[3];
    const float* dw1 = (const float*)d_in[4];
    const float* db1 = (const float*)d_in[5];
    const float* dw2 = (const float*)d_in[6];
    const float* db2 = (const float*)d_in[7];
    const float* dw3 = (const float*)d_in[8];
    const float* db3 = (const float*)d_in[9];
    const float* pw1 = (const float*)d_in[10];
    const float* pb1 = (const float*)d_in[11];
    const float* pw2 = (const float*)d_in[12];
    const float* pb2 = (const float*)d_in[13];
    const float* pw3 = (const float*)d_in[14];
    const float* pb3 = (const float*)d_in[15];

    float *p_dualin, *p_primalin, *p_tmp1d, *p_tmp1p, *p_tmp2, *p_wd, *p_wp;
    cudaGetSymbolAddress((void**)&p_dualin,   g_dualin);
    cudaGetSymbolAddress((void**)&p_primalin, g_primalin);
    cudaGetSymbolAddress((void**)&p_tmp1d,    g_tmp1d);
    cudaGetSymbolAddress((void**)&p_tmp1p,    g_tmp1p);
    cudaGetSymbolAddress((void**)&p_tmp2,     g_tmp2);
    cudaGetSymbolAddress((void**)&p_wd,       g_wdup_d);
    cudaGetSymbolAddress((void**)&p_wp,       g_wdup_p);

    cudaFuncSetAttribute(radon_fwd_kernel, cudaFuncAttributeMaxDynamicSharedMemorySize, 65536);
    cudaFuncSetAttribute(radon_adj_kernel, cudaFuncAttributeMaxDynamicSharedMemorySize, 49152);

    init_kernel<<<512, 256>>>(y);
    pack_weights_kernel<<<36, 256>>>(dw2, p_wd);
    pack_weights_kernel<<<36, 256>>>(pw2, p_wp);

    for (int it = 0; it < NITER; it++) {
        // dual branch
        radon_fwd_kernel<<<dim3(Aa, Bn), 128, 65536>>>();
        conv1_kernel<7, Aa><<<dim3(AD/256, Bn), 256>>>(p_dualin, dw1, db1, p_tmp1d);
        conv2_f32x2_kernel<Aa><<<dim3(Aa, Bn), 64>>>(p_tmp1d, p_wd, db2, p_tmp2);
        conv_dual_update_kernel<<<dim3(AD/256, Bn), 256>>>(p_tmp2, dw3, db3, sigma);
        // primal branch
        radon_adj_kernel<<<dim3(32, Bn), 256, 49152>>>();
        conv1_kernel<6, Hh><<<dim3(HW/256, Bn), 256>>>(p_primalin, pw1, pb1, p_tmp1p);
        conv2_f32x2_kernel<Hh><<<dim3(Hh, Bn), 64>>>(p_tmp1p, p_wp, pb2, p_tmp2);
        conv_primal_update_kernel<<<dim3(HW/256, Bn), 256>>>(p_tmp2, pw3, pb3, tau, theta);
    }

    output_kernel<<<(Bn*HW + 255)/256, 256>>>((float*)d_out);
}

// round 14
// speedup vs baseline: 1.0036x; 1.0036x over previous
#include <cuda_runtime.h>
#include <math.h>

#define Bn 4
#define Hh 128
#define Ww 128
#define Aa 96
#define Dd 128
#define Tt 182
#define NITER 10
#define OPN 128.0f

#define HW (Hh*Ww)      // 16384
#define AD (Aa*Dd)      // 12288
#define WP 144          // padded row stride for conv2 inputs (4 left, 12 right pad)

// ---------------- persistent device state ----------------
__device__ __align__(16) float g_dualin[Bn*7*AD];    // ch0-4 dual, ch5 evalop, ch6 y
__device__ __align__(16) float g_primalin[Bn*6*HW];  // ch0-4 primal, ch5 evalop_adj
__device__ __align__(16) float g_pbar[Bn*5*HW];      // primal_bar
__device__ __align__(16) float g_tmp1d[Bn*32*(Aa+2)*WP];  // padded conv1 out (dual)
__device__ __align__(16) float g_tmp1p[Bn*32*(Hh+2)*WP];  // padded conv1 out (primal)
__device__ __align__(16) float g_tmp2[Bn*32*HW];          // conv2 out (unpadded)
__device__ __align__(16) float g_wdup_d[9*32*32*2];  // dup-packed dual conv2 weights
__device__ __align__(16) float g_wdup_p[9*32*32*2];  // dup-packed primal conv2 weights
__device__ float g_cos[Aa], g_sin[Aa];

// ---------------- f32x2 helpers ----------------
__device__ __forceinline__ unsigned long long pack_hi_lo(unsigned long long a, unsigned long long b) {
    // result = ( lo = hi(a), hi = lo(b) )
    unsigned long long r;
    asm("{\n\t"
        ".reg .b32 al, ah, bl, bh;\n\t"
        "mov.b64 {al, ah}, %1;\n\t"
        "mov.b64 {bl, bh}, %2;\n\t"
        "mov.b64 %0, {ah, bl};\n\t"
        "}" : "=l"(r) : "l"(a), "l"(b));
    return r;
}
__device__ __forceinline__ unsigned long long pack_dup(float v) {
    unsigned long long r;
    unsigned int u = __float_as_uint(v);
    asm("mov.b64 %0, {%1, %1};" : "=l"(r) : "r"(u));
    return r;
}
__device__ __forceinline__ void fma2(unsigned long long& d, unsigned long long a, unsigned long long b) {
    asm("fma.rn.f32x2 %0, %1, %2, %0;" : "+l"(d) : "l"(a), "l"(b));
}

// ---------------- init ----------------
__global__ void init_kernel(const float* __restrict__ y) {
    int i = blockIdx.x*blockDim.x + threadIdx.x;
    int stride = gridDim.x*blockDim.x;
    const int N1 = Bn*7*AD, N2 = Bn*6*HW, N3 = Bn*5*HW;
    const int N4 = Bn*32*(Aa+2)*WP, N5 = Bn*32*(Hh+2)*WP;
    for (int idx = i; idx < N1; idx += stride) {
        int b = idx / (7*AD);
        int r = idx % (7*AD);
        int c = r / AD;
        int p = r % AD;
        g_dualin[idx] = (c == 6) ? y[b*AD + p] : 0.0f;
    }
    for (int idx = i; idx < N2; idx += stride) g_primalin[idx] = 0.0f;
    for (int idx = i; idx < N3; idx += stride) g_pbar[idx]     = 0.0f;
    for (int idx = i; idx < N4; idx += stride) g_tmp1d[idx]    = 0.0f;
    for (int idx = i; idx < N5; idx += stride) g_tmp1p[idx]    = 0.0f;
    if (i < Aa) {
        float ang = (float)((double)i * 3.14159265358979323846 / 96.0);
        g_cos[i] = (float)cos((double)ang);
        g_sin[i] = (float)sin((double)ang);
    }
}

// ---------------- weight dup-packer: HWIO (3,3,32,32) -> [ky][ci][kx][co][2] ----------------
__global__ void pack_weights_kernel(const float* __restrict__ w, float* __restrict__ wdup) {
    int i = blockIdx.x*blockDim.x + threadIdx.x;
    if (i >= 9*32*32) return;
    int co = i & 31;
    int r  = i >> 5;
    int kx = r % 3;  r /= 3;
    int ci = r % 32;
    int ky = r / 32;
    float v = w[((ky*3 + kx)*32 + ci)*32 + co];
    int o = ((ky*32 + ci)*3 + kx)*64 + co*2;
    wdup[o]   = v;
    wdup[o+1] = v;
}

// ---------------- radon forward: pbar ch1 -> dualin ch5 ----------------
extern __shared__ float s_dyn[];
__global__ __launch_bounds__(128) void radon_fwd_kernel() {
    float* simg = s_dyn;
    int a = blockIdx.x, b = blockIdx.y, tid = threadIdx.x;
    const float* img = g_pbar + (b*5 + 1)*HW;
    float4* s4 = (float4*)simg;
    const float4* i4 = (const float4*)img;
    for (int i = tid; i < HW/4; i += 128) s4[i] = i4[i];
    __syncthreads();

    float c  = g_cos[a];
    float sn = g_sin[a];
    float sv = (float)tid - 63.5f;
    float acc = 0.0f;
    #pragma unroll 2
    for (int t = 0; t < Tt; t++) {
        float tv = (float)t - 90.5f;
        float xi = sv*c  - tv*sn + 63.5f;
        float yi = sv*sn + tv*c  + 63.5f;
        float x0f = floorf(xi), y0f = floorf(yi);
        float wx = xi - x0f, wy = yi - y0f;
        int x0 = (int)x0f, y0 = (int)y0f;
        int x1 = x0 + 1, y1 = y0 + 1;
        bool vx0 = (x0 >= 0) & (x0 < Ww);
        bool vx1 = (x1 >= 0) & (x1 < Ww);
        bool vy0 = (y0 >= 0) & (y0 < Hh);
        bool vy1 = (y1 >= 0) & (y1 < Hh);
        int cx0 = min(max(x0,0),Ww-1), cx1 = min(max(x1,0),Ww-1);
        int cy0 = min(max(y0,0),Hh-1), cy1 = min(max(y1,0),Hh-1);
        float v00 = (vx0 && vy0) ? simg[cy0*Ww+cx0] : 0.0f;
        float v01 = (vx1 && vy0) ? simg[cy0*Ww+cx1] : 0.0f;
        float v10 = (vx0 && vy1) ? simg[cy1*Ww+cx0] : 0.0f;
        float v11 = (vx1 && vy1) ? simg[cy1*Ww+cx1] : 0.0f;
        acc += v00*(1.0f-wy)*(1.0f-wx) + v01*(1.0f-wy)*wx
             + v10*wy*(1.0f-wx)        + v11*wy*wx;
    }
    g_dualin[(b*7 + 5)*AD + a*Dd + tid] = acc * (1.0f/OPN);
}

// ---------------- radon adjoint: dualin ch0 -> primalin ch5 ----------------
__global__ __launch_bounds__(256) void radon_adj_kernel() {
    float* ssino = s_dyn;
    int b = blockIdx.y, tid = threadIdx.x;
    const float* sino = g_dualin + (b*7 + 0)*AD;
    float4* s4 = (float4*)ssino;
    const float4* i4 = (const float4*)sino;
    for (int i = tid; i < AD/4; i += 256) s4[i] = i4[i];
    __syncthreads();

    #pragma unroll
    for (int pp = 0; pp < 2; pp++) {
        int p = (blockIdx.x*2 + pp)*256 + tid;
        int yy = p >> 7, xx = p & 127;
        float px = (float)xx - 63.5f;
        float py = (float)yy - 63.5f;
        float acc = 0.0f;
        for (int a = 0; a < Aa; a++) {
            float det = px*g_cos[a] + py*g_sin[a] + 63.5f;
            float d0f = floorf(det);
            float w = det - d0f;
            int d0 = (int)d0f;
            int d1 = d0 + 1;
            float v0 = (d0 >= 0 && d0 < Dd) ? ssino[a*Dd + d0] : 0.0f;
            float v1 = (d1 >= 0 && d1 < Dd) ? ssino[a*Dd + d1] : 0.0f;
            acc += v0*(1.0f-w) + v1*w;
        }
        g_primalin[(b*6 + 5)*HW + p] = acc * (1.0f/OPN);
    }
}

// ---------------- conv1: 3x3 (CIN->32) + relu, unpadded in -> PADDED out ----------------
template<int CIN, int HH>
__global__ __launch_bounds__(256) void conv1_kernel(
    const float* __restrict__ in, const float* __restrict__ w,
    const float* __restrict__ bias, float* __restrict__ out)
{
    __shared__ float sw[9*CIN*32];
    __shared__ float sb[32];
    const int NPIX = HH*128;
    int tid = threadIdx.x;
    for (int i = tid; i < 9*CIN*32; i += 256) sw[i] = w[i];
    if (tid < 32) sb[tid] = bias[tid];
    __syncthreads();

    int b = blockIdx.y;
    int p = blockIdx.x*256 + tid;
    int y = p >> 7, x = p & 127;
    const float* inb = in + b*CIN*NPIX;

    float acc[32];
    #pragma unroll
    for (int co = 0; co < 32; co++) acc[co] = sb[co];

    #pragma unroll
    for (int ky = 0; ky < 3; ky++) {
        int iy = y + ky - 1;
        if (iy < 0 || iy >= HH) continue;
        #pragma unroll
        for (int kx = 0; kx < 3; kx++) {
            int ix = x + kx - 1;
            if (ix < 0 || ix >= 128) continue;
            const float* ip = inb + iy*128 + ix;
            const float* wp = sw + (ky*3 + kx)*CIN*32;
            for (int ci = 0; ci < CIN; ci++) {
                float v = __ldg(ip + ci*NPIX);
                const float4* wr = (const float4*)(wp + ci*32);
                #pragma unroll
                for (int q = 0; q < 8; q++) {
                    float4 wv = wr[q];
                    acc[4*q+0] += v*wv.x;
                    acc[4*q+1] += v*wv.y;
                    acc[4*q+2] += v*wv.z;
                    acc[4*q+3] += v*wv.w;
                }
            }
        }
    }
    // padded output: plane (HH+2)*WP, row y+1, col x+4
    float* ob = out + (b*32)*(HH+2)*WP + (y+1)*WP + x + 4;
    #pragma unroll
    for (int co = 0; co < 32; co++) ob[co*(HH+2)*WP] = fmaxf(acc[co], 0.0f);
}

// ---------------- conv2: 3x3 32->32 + relu, f32x2 packed, padded in -> unpadded out ----
// block = 64 threads: 16 pixel-groups (8 px each) x 4 co-groups (8 co each)
// grid = (HH, Bn)
template<int HH>
__global__ __launch_bounds__(64) void conv2_f32x2_kernel(
    const float* __restrict__ in,    // padded [B][32][HH+2][WP]
    const float* __restrict__ wdup,  // [ky][ci][kx][co][2]
    const float* __restrict__ bias,
    float* __restrict__ out)         // [B][32][HH][128]
{
    const int PLANE = (HH+2)*WP;
    int tid = threadIdx.x;
    int pxg = tid >> 2;          // 0..15
    int cg  = tid & 3;           // 0..3
    int x0  = pxg << 3;
    int y   = blockIdx.x;
    int b   = blockIdx.y;

    unsigned long long acc[8][4];
    #pragma unroll
    for (int j = 0; j < 8; j++) {
        unsigned long long bb = pack_dup(__ldg(&bias[cg*8 + j]));
        #pragma unroll
        for (int k = 0; k < 4; k++) acc[j][k] = bb;
    }

    // pointer to (ch0, row y-1+1=y in padded idx, col x0-4): the +4 col pad and
    // the -4 left-read cancel, so base = row start + x0.
    const float* rowbase = in + (b*32)*PLANE + y*WP + x0;

    #pragma unroll 1
    for (int ky = 0; ky < 3; ky++) {
        const float* r = rowbase + ky*WP;   // padded row index y+ky = logical row y+ky-1
        const float* wk = wdup + (ky*32)*3*64 + cg*16;
        #pragma unroll 2
        for (int ci = 0; ci < 32; ci++) {
            const ulonglong2* u = (const ulonglong2*)(r + ci*PLANE);   // cols x0-4 ..
            ulonglong2 U0 = u[0];   // P-2, P-1   (cols x0-4..x0-1)
            ulonglong2 U1 = u[1];   // P0,  P1    (x0..x0+3)
            ulonglong2 U2 = u[2];   // P2,  P3    (x0+4..x0+7)
            ulonglong2 U3 = u[3];   // P4,  P5    (x0+8..x0+11)

            unsigned long long S0 = pack_hi_lo(U0.y, U1.x);
            unsigned long long S1 = pack_hi_lo(U1.x, U1.y);
            unsigned long long S2 = pack_hi_lo(U1.y, U2.x);
            unsigned long long S3 = pack_hi_lo(U2.x, U2.y);
            unsigned long long T3 = pack_hi_lo(U2.y, U3.x);

            const ulonglong2* wp = (const ulonglong2*)(wk + ci*3*64);

            #pragma unroll
            for (int kxi = 0; kxi < 3; kxi++) {
                unsigned long long A0, A1, A2, A3;
                if (kxi == 0)      { A0 = S0;   A1 = S1;   A2 = S2;   A3 = S3; }
                else if (kxi == 1) { A0 = U1.x; A1 = U1.y; A2 = U2.x; A3 = U2.y; }
                else               { A0 = S1;   A1 = S2;   A2 = S3;   A3 = T3; }

                ulonglong2 w01 = wp[kxi*16 + 0];
                ulonglong2 w23 = wp[kxi*16 + 1];
                ulonglong2 w45 = wp[kxi*16 + 2];
                ulonglong2 w67 = wp[kxi*16 + 3];

                fma2(acc[0][0], A0, w01.x); fma2(acc[0][1], A1, w01.x);
                fma2(acc[0][2], A2, w01.x); fma2(acc[0][3], A3, w01.x);
                fma2(acc[1][0], A0, w01.y); fma2(acc[1][1], A1, w01.y);
                fma2(acc[1][2], A2, w01.y); fma2(acc[1][3], A3, w01.y);
                fma2(acc[2][0], A0, w23.x); fma2(acc[2][1], A1, w23.x);
                fma2(acc[2][2], A2, w23.x); fma2(acc[2][3], A3, w23.x);
                fma2(acc[3][0], A0, w23.y); fma2(acc[3][1], A1, w23.y);
                fma2(acc[3][2], A2, w23.y); fma2(acc[3][3], A3, w23.y);
                fma2(acc[4][0], A0, w45.x); fma2(acc[4][1], A1, w45.x);
                fma2(acc[4][2], A2, w45.x); fma2(acc[4][3], A3, w45.x);
                fma2(acc[5][0], A0, w45.y); fma2(acc[5][1], A1, w45.y);
                fma2(acc[5][2], A2, w45.y); fma2(acc[5][3], A3, w45.y);
                fma2(acc[6][0], A0, w67.x); fma2(acc[6][1], A1, w67.x);
                fma2(acc[6][2], A2, w67.x); fma2(acc[6][3], A3, w67.x);
                fma2(acc[7][0], A0, w67.y); fma2(acc[7][1], A1, w67.y);
                fma2(acc[7][2], A2, w67.y); fma2(acc[7][3], A3, w67.y);
            }
        }
    }

    #pragma unroll
    for (int j = 0; j < 8; j++) {
        int co = cg*8 + j;
        float2* op = (float2*)(out + ((b*32 + co)*HH + y)*128 + x0);
        #pragma unroll
        for (int k = 0; k < 4; k++) {
            unsigned long long a = acc[j][k];
            float lo = __uint_as_float((unsigned int)a);
            float hi = __uint_as_float((unsigned int)(a >> 32));
            float2 v;
            v.x = fmaxf(lo, 0.0f);
            v.y = fmaxf(hi, 0.0f);
            op[k] = v;
        }
    }
}

// ---------------- conv3x3 (32->5) + dual update ----------------
__global__ __launch_bounds__(256) void conv_dual_update_kernel(
    const float* __restrict__ in, const float* __restrict__ w,
    const float* __restrict__ bias, const float* __restrict__ sigma)
{
    __shared__ float sw[9*32*5];
    __shared__ float sb[5];
    int tid = threadIdx.x;
    for (int i = tid; i < 9*32*5; i += 256) sw[i] = w[i];
    if (tid < 5) sb[tid] = bias[tid];
    __syncthreads();

    int b = blockIdx.y;
    int p = blockIdx.x*256 + tid;
    int y = p >> 7, x = p & 127;
    const float* inb = in + b*32*AD;

    float acc[5];
    #pragma unroll
    for (int co = 0; co < 5; co++) acc[co] = sb[co];

    #pragma unroll
    for (int ky = 0; ky < 3; ky++) {
        int iy = y + ky - 1;
        if (iy < 0 || iy >= Aa) continue;
        #pragma unroll
        for (int kx = 0; kx < 3; kx++) {
            int ix = x + kx - 1;
            if (ix < 0 || ix >= 128) continue;
            const float* ip = inb + iy*128 + ix;
            const float* wp = sw + (ky*3 + kx)*32*5;
            for (int ci = 0; ci < 32; ci++) {
                float v = __ldg(ip + ci*AD);
                const float* wr = wp + ci*5;
                #pragma unroll
                for (int co = 0; co < 5; co++) acc[co] += v*wr[co];
            }
        }
    }
    float sg = __ldg(sigma);
    #pragma unroll
    for (int co = 0; co < 5; co++) {
        float* dp = g_dualin + (b*7 + co)*AD + p;
        *dp = *dp + sg*acc[co];
    }
}

// ---------------- conv3x3 (32->5) + primal & pbar update ----------------
__global__ __launch_bounds__(256) void conv_primal_update_kernel(
    const float* __restrict__ in, const float* __restrict__ w,
    const float* __restrict__ bias, const float* __restrict__ tau,
    const float* __restrict__ theta)
{
    __shared__ float sw[9*32*5];
    __shared__ float sb[5];
    int tid = threadIdx.x;
    for (int i = tid; i < 9*32*5; i += 256) sw[i] = w[i];
    if (tid < 5) sb[tid] = bias[tid];
    __syncthreads();

    int b = blockIdx.y;
    int p = blockIdx.x*256 + tid;
    int y = p >> 7, x = p & 127;
    const float* inb = in + b*32*HW;

    float acc[5];
    #pragma unroll
    for (int co = 0; co < 5; co++) acc[co] = sb[co];

    #pragma unroll
    for (int ky = 0; ky < 3; ky++) {
        int iy = y + ky - 1;
        if (iy < 0 || iy >= Hh) continue;
        #pragma unroll
        for (int kx = 0; kx < 3; kx++) {
            int ix = x + kx - 1;
            if (ix < 0 || ix >= 128) continue;
            const float* ip = inb + iy*128 + ix;
            const float* wp = sw + (ky*3 + kx)*32*5;
            for (int ci = 0; ci < 32; ci++) {
                float v = __ldg(ip + ci*HW);
                const float* wr = wp + ci*5;
                #pragma unroll
                for (int co = 0; co < 5; co++) acc[co] += v*wr[co];
            }
        }
    }
    float tv = __ldg(tau);
    float th = __ldg(theta);
    #pragma unroll
    for (int co = 0; co < 5; co++) {
        float* pp = g_primalin + (b*6 + co)*HW + p;
        float oldv = *pp;
        float nv = oldv + tv*acc[co];
        *pp = nv;
        g_pbar[(b*5 + co)*HW + p] = nv + th*(nv - oldv);
    }
}

// ---------------- output ----------------
__global__ void output_kernel(float* __restrict__ out) {
    int i = blockIdx.x*blockDim.x + threadIdx.x;
    if (i < Bn*HW) {
        int b = i / HW, p = i % HW;
        out[i] = g_primalin[(b*6 + 0)*HW + p];
    }
}

// ---------------- launch ----------------
extern "C" void kernel_launch(void* const* d_in, const int* in_sizes, int n_in,
                              void* d_out, int out_size)
{
    const float* y     = (const float*)d_in[0];
    const float* sigma = (const float*)d_in[1];
    const float* tau   = (const float*)d_in[2];
    const float* theta = (const float*)d_in[3];
    const float* dw1 = (const float*)d_in[4];
    const float* db1 = (const float*)d_in[5];
    const float* dw2 = (const float*)d_in[6];
    const float* db2 = (const float*)d_in[7];
    const float* dw3 = (const float*)d_in[8];
    const float* db3 = (const float*)d_in[9];
    const float* pw1 = (const float*)d_in[10];
    const float* pb1 = (const float*)d_in[11];
    const float* pw2 = (const float*)d_in[12];
    const float* pb2 = (const float*)d_in[13];
    const float* pw3 = (const float*)d_in[14];
    const float* pb3 = (const float*)d_in[15];

    float *p_dualin, *p_primalin, *p_tmp1d, *p_tmp1p, *p_tmp2, *p_wd, *p_wp;
    cudaGetSymbolAddress((void**)&p_dualin,   g_dualin);
    cudaGetSymbolAddress((void**)&p_primalin, g_primalin);
    cudaGetSymbolAddress((void**)&p_tmp1d,    g_tmp1d);
    cudaGetSymbolAddress((void**)&p_tmp1p,    g_tmp1p);
    cudaGetSymbolAddress((void**)&p_tmp2,     g_tmp2);
    cudaGetSymbolAddress((void**)&p_wd,       g_wdup_d);
    cudaGetSymbolAddress((void**)&p_wp,       g_wdup_p);

    cudaFuncSetAttribute(radon_fwd_kernel, cudaFuncAttributeMaxDynamicSharedMemorySize, 65536);
    cudaFuncSetAttribute(radon_adj_kernel, cudaFuncAttributeMaxDynamicSharedMemorySize, 49152);

    init_kernel<<<512, 256>>>(y);
    pack_weights_kernel<<<36, 256>>>(dw2, p_wd);
    pack_weights_kernel<<<36, 256>>>(pw2, p_wp);

    for (int it = 0; it < NITER; it++) {
        // dual branch
        radon_fwd_kernel<<<dim3(Aa, Bn), 128, 65536>>>();
        conv1_kernel<7, Aa><<<dim3(AD/256, Bn), 256>>>(p_dualin, dw1, db1, p_tmp1d);
        conv2_f32x2_kernel<Aa><<<dim3(Aa, Bn), 64>>>(p_tmp1d, p_wd, db2, p_tmp2);
        conv_dual_update_kernel<<<dim3(AD/256, Bn), 256>>>(p_tmp2, dw3, db3, sigma);
        // primal branch
        radon_adj_kernel<<<dim3(32, Bn), 256, 49152>>>();
        conv1_kernel<6, Hh><<<dim3(HW/256, Bn), 256>>>(p_primalin, pw1, pb1, p_tmp1p);
        conv2_f32x2_kernel<Hh><<<dim3(Hh, Bn), 64>>>(p_tmp1p, p_wp, pb2, p_tmp2);
        conv_primal_update_kernel<<<dim3(HW/256, Bn), 256>>>(p_tmp2, pw3, pb3, tau, theta);
    }

    output_kernel<<<(Bn*HW + 255)/256, 256>>>((float*)d_out);
}

// round 15
// speedup vs baseline: 1.0075x; 1.0038x over previous
#include <cuda_runtime.h>
#include <math.h>

#define Bn 4
#define Hh 128
#define Ww 128
#define Aa 96
#define Dd 128
#define Tt 182
#define NITER 10
#define OPN 128.0f

#define HW (Hh*Ww)      // 16384
#define AD (Aa*Dd)      // 12288
#define WP 144          // padded row stride for conv2 inputs (4 left, 12 right pad)

// ---------------- persistent device state ----------------
__device__ __align__(16) float g_dualin[Bn*7*AD];    // ch0-4 dual, ch5 evalop, ch6 y
__device__ __align__(16) float g_primalin[Bn*6*HW];  // ch0-4 primal, ch5 evalop_adj
__device__ __align__(16) float g_pbar[Bn*5*HW];      // primal_bar
__device__ __align__(16) float g_tmp1d[Bn*32*(Aa+2)*WP];  // padded conv1 out (dual)
__device__ __align__(16) float g_tmp1p[Bn*32*(Hh+2)*WP];  // padded conv1 out (primal)
__device__ __align__(16) float g_tmp2[Bn*32*HW];          // conv2 out (unpadded)
__device__ __align__(16) float g_wdup_d[9*32*32*2];  // dup-packed dual conv2 weights
__device__ __align__(16) float g_wdup_p[9*32*32*2];  // dup-packed primal conv2 weights
__device__ float g_cos[Aa], g_sin[Aa];

// ---------------- f32x2 helpers ----------------
__device__ __forceinline__ unsigned long long pack_hi_lo(unsigned long long a, unsigned long long b) {
    // result = ( lo = hi(a), hi = lo(b) )
    unsigned long long r;
    asm("{\n\t"
        ".reg .b32 al, ah, bl, bh;\n\t"
        "mov.b64 {al, ah}, %1;\n\t"
        "mov.b64 {bl, bh}, %2;\n\t"
        "mov.b64 %0, {ah, bl};\n\t"
        "}" : "=l"(r) : "l"(a), "l"(b));
    return r;
}
__device__ __forceinline__ unsigned long long pack_dup(float v) {
    unsigned long long r;
    unsigned int u = __float_as_uint(v);
    asm("mov.b64 %0, {%1, %1};" : "=l"(r) : "r"(u));
    return r;
}
__device__ __forceinline__ void fma2(unsigned long long& d, unsigned long long a, unsigned long long b) {
    asm("fma.rn.f32x2 %0, %1, %2, %0;" : "+l"(d) : "l"(a), "l"(b));
}

// ---------------- init ----------------
__global__ void init_kernel(const float* __restrict__ y) {
    int i = blockIdx.x*blockDim.x + threadIdx.x;
    int stride = gridDim.x*blockDim.x;
    const int N1 = Bn*7*AD, N2 = Bn*6*HW, N3 = Bn*5*HW;
    const int N4 = Bn*32*(Aa+2)*WP, N5 = Bn*32*(Hh+2)*WP;
    for (int idx = i; idx < N1; idx += stride) {
        int b = idx / (7*AD);
        int r = idx % (7*AD);
        int c = r / AD;
        int p = r % AD;
        g_dualin[idx] = (c == 6) ? y[b*AD + p] : 0.0f;
    }
    for (int idx = i; idx < N2; idx += stride) g_primalin[idx] = 0.0f;
    for (int idx = i; idx < N3; idx += stride) g_pbar[idx]     = 0.0f;
    for (int idx = i; idx < N4; idx += stride) g_tmp1d[idx]    = 0.0f;
    for (int idx = i; idx < N5; idx += stride) g_tmp1p[idx]    = 0.0f;
    if (i < Aa) {
        float ang = (float)((double)i * 3.14159265358979323846 / 96.0);
        g_cos[i] = (float)cos((double)ang);
        g_sin[i] = (float)sin((double)ang);
    }
}

// ---------------- weight dup-packer: HWIO (3,3,32,32) -> [ky][ci][kx][co][2] ----------------
__global__ void pack_weights_kernel(const float* __restrict__ w, float* __restrict__ wdup) {
    int i = blockIdx.x*blockDim.x + threadIdx.x;
    if (i >= 9*32*32) return;
    int co = i & 31;
    int r  = i >> 5;
    int kx = r % 3;  r /= 3;
    int ci = r % 32;
    int ky = r / 32;
    float v = w[((ky*3 + kx)*32 + ci)*32 + co];
    int o = ((ky*32 + ci)*3 + kx)*64 + co*2;
    wdup[o]   = v;
    wdup[o+1] = v;
}

// ---------------- radon forward: pbar ch1 -> dualin ch5 ----------------
extern __shared__ float s_dyn[];
__global__ __launch_bounds__(128) void radon_fwd_kernel() {
    float* simg = s_dyn;
    int a = blockIdx.x, b = blockIdx.y, tid = threadIdx.x;
    const float* img = g_pbar + (b*5 + 1)*HW;
    float4* s4 = (float4*)simg;
    const float4* i4 = (const float4*)img;
    for (int i = tid; i < HW/4; i += 128) s4[i] = i4[i];
    __syncthreads();

    float c  = g_cos[a];
    float sn = g_sin[a];
    float sv = (float)tid - 63.5f;
    float acc = 0.0f;
    #pragma unroll 2
    for (int t = 0; t < Tt; t++) {
        float tv = (float)t - 90.5f;
        float xi = sv*c  - tv*sn + 63.5f;
        float yi = sv*sn + tv*c  + 63.5f;
        float x0f = floorf(xi), y0f = floorf(yi);
        float wx = xi - x0f, wy = yi - y0f;
        int x0 = (int)x0f, y0 = (int)y0f;
        int x1 = x0 + 1, y1 = y0 + 1;
        bool vx0 = (x0 >= 0) & (x0 < Ww);
        bool vx1 = (x1 >= 0) & (x1 < Ww);
        bool vy0 = (y0 >= 0) & (y0 < Hh);
        bool vy1 = (y1 >= 0) & (y1 < Hh);
        int cx0 = min(max(x0,0),Ww-1), cx1 = min(max(x1,0),Ww-1);
        int cy0 = min(max(y0,0),Hh-1), cy1 = min(max(y1,0),Hh-1);
        float v00 = (vx0 && vy0) ? simg[cy0*Ww+cx0] : 0.0f;
        float v01 = (vx1 && vy0) ? simg[cy0*Ww+cx1] : 0.0f;
        float v10 = (vx0 && vy1) ? simg[cy1*Ww+cx0] : 0.0f;
        float v11 = (vx1 && vy1) ? simg[cy1*Ww+cx1] : 0.0f;
        acc += v00*(1.0f-wy)*(1.0f-wx) + v01*(1.0f-wy)*wx
             + v10*wy*(1.0f-wx)        + v11*wy*wx;
    }
    g_dualin[(b*7 + 5)*AD + a*Dd + tid] = acc * (1.0f/OPN);
}

// ---------------- radon adjoint: dualin ch0 -> primalin ch5 ----------------
__global__ __launch_bounds__(256) void radon_adj_kernel() {
    float* ssino = s_dyn;
    int b = blockIdx.y, tid = threadIdx.x;
    const float* sino = g_dualin + (b*7 + 0)*AD;
    float4* s4 = (float4*)ssino;
    const float4* i4 = (const float4*)sino;
    for (int i = tid; i < AD/4; i += 256) s4[i] = i4[i];
    __syncthreads();

    #pragma unroll
    for (int pp = 0; pp < 2; pp++) {
        int p = (blockIdx.x*2 + pp)*256 + tid;
        int yy = p >> 7, xx = p & 127;
        float px = (float)xx - 63.5f;
        float py = (float)yy - 63.5f;
        float acc = 0.0f;
        for (int a = 0; a < Aa; a++) {
            float det = px*g_cos[a] + py*g_sin[a] + 63.5f;
            float d0f = floorf(det);
            float w = det - d0f;
            int d0 = (int)d0f;
            int d1 = d0 + 1;
            float v0 = (d0 >= 0 && d0 < Dd) ? ssino[a*Dd + d0] : 0.0f;
            float v1 = (d1 >= 0 && d1 < Dd) ? ssino[a*Dd + d1] : 0.0f;
            acc += v0*(1.0f-w) + v1*w;
        }
        g_primalin[(b*6 + 5)*HW + p] = acc * (1.0f/OPN);
    }
}

// ---------------- conv1: 3x3 (CIN->32) + relu, unpadded in -> PADDED out ----------------
template<int CIN, int HH>
__global__ __launch_bounds__(256) void conv1_kernel(
    const float* __restrict__ in, const float* __restrict__ w,
    const float* __restrict__ bias, float* __restrict__ out)
{
    __shared__ float sw[9*CIN*32];
    __shared__ float sb[32];
    const int NPIX = HH*128;
    int tid = threadIdx.x;
    for (int i = tid; i < 9*CIN*32; i += 256) sw[i] = w[i];
    if (tid < 32) sb[tid] = bias[tid];
    __syncthreads();

    int b = blockIdx.y;
    int p = blockIdx.x*256 + tid;
    int y = p >> 7, x = p & 127;
    const float* inb = in + b*CIN*NPIX;

    float acc[32];
    #pragma unroll
    for (int co = 0; co < 32; co++) acc[co] = sb[co];

    #pragma unroll
    for (int ky = 0; ky < 3; ky++) {
        int iy = y + ky - 1;
        if (iy < 0 || iy >= HH) continue;
        #pragma unroll
        for (int kx = 0; kx < 3; kx++) {
            int ix = x + kx - 1;
            if (ix < 0 || ix >= 128) continue;
            const float* ip = inb + iy*128 + ix;
            const float* wp = sw + (ky*3 + kx)*CIN*32;
            for (int ci = 0; ci < CIN; ci++) {
                float v = __ldg(ip + ci*NPIX);
                const float4* wr = (const float4*)(wp + ci*32);
                #pragma unroll
                for (int q = 0; q < 8; q++) {
                    float4 wv = wr[q];
                    acc[4*q+0] += v*wv.x;
                    acc[4*q+1] += v*wv.y;
                    acc[4*q+2] += v*wv.z;
                    acc[4*q+3] += v*wv.w;
                }
            }
        }
    }
    // padded output: plane (HH+2)*WP, row y+1, col x+4
    float* ob = out + (b*32)*(HH+2)*WP + (y+1)*WP + x + 4;
    #pragma unroll
    for (int co = 0; co < 32; co++) ob[co*(HH+2)*WP] = fmaxf(acc[co], 0.0f);
}

// ---------------- conv2: 3x3 32->32 + relu, f32x2 packed, padded in -> unpadded out ----
// block = 64 threads: 16 pixel-groups (8 px each) x 4 co-groups (8 co each)
// grid = (HH, Bn)
template<int HH>
__global__ __launch_bounds__(64) void conv2_f32x2_kernel(
    const float* __restrict__ in,    // padded [B][32][HH+2][WP]
    const float* __restrict__ wdup,  // [ky][ci][kx][co][2]
    const float* __restrict__ bias,
    float* __restrict__ out)         // [B][32][HH][128]
{
    const int PLANE = (HH+2)*WP;
    int tid = threadIdx.x;
    int pxg = tid >> 2;          // 0..15
    int cg  = tid & 3;           // 0..3
    int x0  = pxg << 3;
    int y   = blockIdx.x;
    int b   = blockIdx.y;

    unsigned long long acc[8][4];
    #pragma unroll
    for (int j = 0; j < 8; j++) {
        unsigned long long bb = pack_dup(__ldg(&bias[cg*8 + j]));
        #pragma unroll
        for (int k = 0; k < 4; k++) acc[j][k] = bb;
    }

    // pointer to (ch0, row y-1+1=y in padded idx, col x0-4): the +4 col pad and
    // the -4 left-read cancel, so base = row start + x0.
    const float* rowbase = in + (b*32)*PLANE + y*WP + x0;

    #pragma unroll 1
    for (int ky = 0; ky < 3; ky++) {
        const float* r = rowbase + ky*WP;   // padded row index y+ky = logical row y+ky-1
        const float* wk = wdup + (ky*32)*3*64 + cg*16;
        #pragma unroll 2
        for (int ci = 0; ci < 32; ci++) {
            const ulonglong2* u = (const ulonglong2*)(r + ci*PLANE);   // cols x0-4 ..
            ulonglong2 U0 = u[0];   // P-2, P-1   (cols x0-4..x0-1)
            ulonglong2 U1 = u[1];   // P0,  P1    (x0..x0+3)
            ulonglong2 U2 = u[2];   // P2,  P3    (x0+4..x0+7)
            ulonglong2 U3 = u[3];   // P4,  P5    (x0+8..x0+11)

            unsigned long long S0 = pack_hi_lo(U0.y, U1.x);
            unsigned long long S1 = pack_hi_lo(U1.x, U1.y);
            unsigned long long S2 = pack_hi_lo(U1.y, U2.x);
            unsigned long long S3 = pack_hi_lo(U2.x, U2.y);
            unsigned long long T3 = pack_hi_lo(U2.y, U3.x);

            const ulonglong2* wp = (const ulonglong2*)(wk + ci*3*64);

            #pragma unroll
            for (int kxi = 0; kxi < 3; kxi++) {
                unsigned long long A0, A1, A2, A3;
                if (kxi == 0)      { A0 = S0;   A1 = S1;   A2 = S2;   A3 = S3; }
                else if (kxi == 1) { A0 = U1.x; A1 = U1.y; A2 = U2.x; A3 = U2.y; }
                else               { A0 = S1;   A1 = S2;   A2 = S3;   A3 = T3; }

                ulonglong2 w01 = wp[kxi*16 + 0];
                ulonglong2 w23 = wp[kxi*16 + 1];
                ulonglong2 w45 = wp[kxi*16 + 2];
                ulonglong2 w67 = wp[kxi*16 + 3];

                fma2(acc[0][0], A0, w01.x); fma2(acc[0][1], A1, w01.x);
                fma2(acc[0][2], A2, w01.x); fma2(acc[0][3], A3, w01.x);
                fma2(acc[1][0], A0, w01.y); fma2(acc[1][1], A1, w01.y);
                fma2(acc[1][2], A2, w01.y); fma2(acc[1][3], A3, w01.y);
                fma2(acc[2][0], A0, w23.x); fma2(acc[2][1], A1, w23.x);
                fma2(acc[2][2], A2, w23.x); fma2(acc[2][3], A3, w23.x);
                fma2(acc[3][0], A0, w23.y); fma2(acc[3][1], A1, w23.y);
                fma2(acc[3][2], A2, w23.y); fma2(acc[3][3], A3, w23.y);
                fma2(acc[4][0], A0, w45.x); fma2(acc[4][1], A1, w45.x);
                fma2(acc[4][2], A2, w45.x); fma2(acc[4][3], A3, w45.x);
                fma2(acc[5][0], A0, w45.y); fma2(acc[5][1], A1, w45.y);
                fma2(acc[5][2], A2, w45.y); fma2(acc[5][3], A3, w45.y);
                fma2(acc[6][0], A0, w67.x); fma2(acc[6][1], A1, w67.x);
                fma2(acc[6][2], A2, w67.x); fma2(acc[6][3], A3, w67.x);
                fma2(acc[7][0], A0, w67.y); fma2(acc[7][1], A1, w67.y);
                fma2(acc[7][2], A2, w67.y); fma2(acc[7][3], A3, w67.y);
            }
        }
    }

    #pragma unroll
    for (int j = 0; j < 8; j++) {
        int co = cg*8 + j;
        float2* op = (float2*)(out + ((b*32 + co)*HH + y)*128 + x0);
        #pragma unroll
        for (int k = 0; k < 4; k++) {
            unsigned long long a = acc[j][k];
            float lo = __uint_as_float((unsigned int)a);
            float hi = __uint_as_float((unsigned int)(a >> 32));
            float2 v;
            v.x = fmaxf(lo, 0.0f);
            v.y = fmaxf(hi, 0.0f);
            op[k] = v;
        }
    }
}

// ---------------- conv3x3 (32->5) + dual update ----------------
__global__ __launch_bounds__(256) void conv_dual_update_kernel(
    const float* __restrict__ in, const float* __restrict__ w,
    const float* __restrict__ bias, const float* __restrict__ sigma)
{
    __shared__ float sw[9*32*5];
    __shared__ float sb[5];
    int tid = threadIdx.x;
    for (int i = tid; i < 9*32*5; i += 256) sw[i] = w[i];
    if (tid < 5) sb[tid] = bias[tid];
    __syncthreads();

    int b = blockIdx.y;
    int p = blockIdx.x*256 + tid;
    int y = p >> 7, x = p & 127;
    const float* inb = in + b*32*AD;

    float acc[5];
    #pragma unroll
    for (int co = 0; co < 5; co++) acc[co] = sb[co];

    #pragma unroll
    for (int ky = 0; ky < 3; ky++) {
        int iy = y + ky - 1;
        if (iy < 0 || iy >= Aa) continue;
        #pragma unroll
        for (int kx = 0; kx < 3; kx++) {
            int ix = x + kx - 1;
            if (ix < 0 || ix >= 128) continue;
            const float* ip = inb + iy*128 + ix;
            const float* wp = sw + (ky*3 + kx)*32*5;
            for (int ci = 0; ci < 32; ci++) {
                float v = __ldg(ip + ci*AD);
                const float* wr = wp + ci*5;
                #pragma unroll
                for (int co = 0; co < 5; co++) acc[co] += v*wr[co];
            }
        }
    }
    float sg = __ldg(sigma);
    #pragma unroll
    for (int co = 0; co < 5; co++) {
        float* dp = g_dualin + (b*7 + co)*AD + p;
        *dp = *dp + sg*acc[co];
    }
}

// ---------------- conv3x3 (32->5) + primal & pbar update ----------------
__global__ __launch_bounds__(256) void conv_primal_update_kernel(
    const float* __restrict__ in, const float* __restrict__ w,
    const float* __restrict__ bias, const float* __restrict__ tau,
    const float* __restrict__ theta)
{
    __shared__ float sw[9*32*5];
    __shared__ float sb[5];
    int tid = threadIdx.x;
    for (int i = tid; i < 9*32*5; i += 256) sw[i] = w[i];
    if (tid < 5) sb[tid] = bias[tid];
    __syncthreads();

    int b = blockIdx.y;
    int p = blockIdx.x*256 + tid;
    int y = p >> 7, x = p & 127;
    const float* inb = in + b*32*HW;

    float acc[5];
    #pragma unroll
    for (int co = 0; co < 5; co++) acc[co] = sb[co];

    #pragma unroll
    for (int ky = 0; ky < 3; ky++) {
        int iy = y + ky - 1;
        if (iy < 0 || iy >= Hh) continue;
        #pragma unroll
        for (int kx = 0; kx < 3; kx++) {
            int ix = x + kx - 1;
            if (ix < 0 || ix >= 128) continue;
            const float* ip = inb + iy*128 + ix;
            const float* wp = sw + (ky*3 + kx)*32*5;
            for (int ci = 0; ci < 32; ci++) {
                float v = __ldg(ip + ci*HW);
                const float* wr = wp + ci*5;
                #pragma unroll
                for (int co = 0; co < 5; co++) acc[co] += v*wr[co];
            }
        }
    }
    float tv = __ldg(tau);
    float th = __ldg(theta);
    #pragma unroll
    for (int co = 0; co < 5; co++) {
        float* pp = g_primalin + (b*6 + co)*HW + p;
        float oldv = *pp;
        float nv = oldv + tv*acc[co];
        *pp = nv;
        g_pbar[(b*5 + co)*HW + p] = nv + th*(nv - oldv);
    }
}

// ---------------- output ----------------
__global__ void output_kernel(float* __restrict__ out) {
    int i = blockIdx.x*blockDim.x + threadIdx.x;
    if (i < Bn*HW) {
        int b = i / HW, p = i % HW;
        out[i] = g_primalin[(b*6 + 0)*HW + p];
    }
}

// ---------------- launch ----------------
extern "C" void kernel_launch(void* const* d_in, const int* in_sizes, int n_in,
                              void* d_out, int out_size)
{
    const float* y     = (const float*)d_in[0];
    const float* sigma = (const float*)d_in[1];
    const float* tau   = (const float*)d_in[2];
    const float* theta = (const float*)d_in[3];
    const float* dw1 = (const float*)d_in[4];
    const float* db1 = (const float*)d_in[5];
    const float* dw2 = (const float*)d_in[6];
    const float* db2 = (const float*)d_in[7];
    const float* dw3 = (const float*)d_in[8];
    const float* db3 = (const float*)d_in[9];
    const float* pw1 = (const float*)d_in[10];
    const float* pb1 = (const float*)d_in[11];
    const float* pw2 = (const float*)d_in[12];
    const float* pb2 = (const float*)d_in[13];
    const float* pw3 = (const float*)d_in[14];
    const float* pb3 = (const float*)d_in[15];

    float *p_dualin, *p_primalin, *p_tmp1d, *p_tmp1p, *p_tmp2, *p_wd, *p_wp;
    cudaGetSymbolAddress((void**)&p_dualin,   g_dualin);
    cudaGetSymbolAddress((void**)&p_primalin, g_primalin);
    cudaGetSymbolAddress((void**)&p_tmp1d,    g_tmp1d);
    cudaGetSymbolAddress((void**)&p_tmp1p,    g_tmp1p);
    cudaGetSymbolAddress((void**)&p_tmp2,     g_tmp2);
    cudaGetSymbolAddress((void**)&p_wd,       g_wdup_d);
    cudaGetSymbolAddress((void**)&p_wp,       g_wdup_p);

    cudaFuncSetAttribute(radon_fwd_kernel, cudaFuncAttributeMaxDynamicSharedMemorySize, 65536);
    cudaFuncSetAttribute(radon_adj_kernel, cudaFuncAttributeMaxDynamicSharedMemorySize, 49152);

    init_kernel<<<512, 256>>>(y);
    pack_weights_kernel<<<36, 256>>>(dw2, p_wd);
    pack_weights_kernel<<<36, 256>>>(pw2, p_wp);

    for (int it = 0; it < NITER; it++) {
        // dual branch
        radon_fwd_kernel<<<dim3(Aa, Bn), 128, 65536>>>();
        conv1_kernel<7, Aa><<<dim3(AD/256, Bn), 256>>>(p_dualin, dw1, db1, p_tmp1d);
        conv2_f32x2_kernel<Aa><<<dim3(Aa, Bn), 64>>>(p_tmp1d, p_wd, db2, p_tmp2);
        conv_dual_update_kernel<<<dim3(AD/256, Bn), 256>>>(p_tmp2, dw3, db3, sigma);
        // primal branch
        radon_adj_kernel<<<dim3(32, Bn), 256, 49152>>>();
        conv1_kernel<6, Hh><<<dim3(HW/256, Bn), 256>>>(p_primalin, pw1, pb1, p_tmp1p);
        conv2_f32x2_kernel<Hh><<<dim3(Hh, Bn), 64>>>(p_tmp1p, p_wp, pb2, p_tmp2);
        conv_primal_update_kernel<<<dim3(HW/256, Bn), 256>>>(p_tmp2, pw3, pb3, tau, theta);
    }

    output_kernel<<<(Bn*HW + 255)/256, 256>>>((float*)d_out);
}